// round 13
// baseline (speedup 1.0000x reference)
#include <cuda_runtime.h>
#include <cuda_bf16.h>

// PropagationOnly_SharedPixel: 12 iterations of
//   u <- tanh(scalar * (const + w[i] * sum_{3x3}(u)))
// on a 64x64 grid, batch 128. 9-point box stencil (hiddenWeight unused).
//
// R13: R7 structure (512 threads, warp = 4 rows, lane = 2 adjacent cols,
// interior-before-halo phase split, double buffer, 1 __syncthreads/iter,
// 4-wide shared-rcp tanh) with PAIR-NATIVE data flow: state and vertical
// sums live as 64-bit packed values end-to-end (LDS.64 in, add2 chains,
// STS.64 out) so ptxas needs no repacking MOVs; the horizontal + tanh stage
// is pure scalar FFMA/MUFU (no fma2 glue).

#define NSIDE 64
#define HPIX  4096
#define ITERS 12
#define SROWS 34           // 32 stored boundary rows + zero row above/below

typedef unsigned long long u64;

__device__ __forceinline__ float ex2_approx(float x) {
    float y; asm("ex2.approx.f32 %0, %1;" : "=f"(y) : "f"(x)); return y;
}
__device__ __forceinline__ float rcp_approx(float x) {
    float y; asm("rcp.approx.f32 %0, %1;" : "=f"(y) : "f"(x)); return y;
}
__device__ __forceinline__ u64 add2(u64 a, u64 b) {
    u64 r; asm("add.rn.f32x2 %0, %1, %2;" : "=l"(r) : "l"(a), "l"(b)); return r;
}
__device__ __forceinline__ u64 pk(float lo, float hi) {
    u64 r; asm("mov.b64 %0, {%1, %2};" : "=l"(r) : "f"(lo), "f"(hi)); return r;
}
__device__ __forceinline__ void upk(u64 v, float& lo, float& hi) {
    asm("mov.b64 {%0, %1}, %2;" : "=f"(lo), "=f"(hi) : "l"(v));
}

// tanh for 4 pixels (scalar) with ONE rcp via prefix/suffix products.
__device__ __forceinline__ void tanh4s(float t0, float t1, float t2, float t3,
                                       float& r0, float& r1, float& r2, float& r3)
{
    t0 = fminf(t0, 24.0f);  t1 = fminf(t1, 24.0f);
    t2 = fminf(t2, 24.0f);  t3 = fminf(t3, 24.0f);
    const float d0 = 1.0f + ex2_approx(t0);
    const float d1 = 1.0f + ex2_approx(t1);
    const float d2 = 1.0f + ex2_approx(t2);
    const float d3 = 1.0f + ex2_approx(t3);
    const float pA = d0 * d1;                   // <= 2^50, finite
    const float pB = d2 * d3;
    const float R  = rcp_approx(pA * pB);       // <= 2^100, finite
    const float RA = R * pB;                    // = 1/pA
    const float RB = R * pA;                    // = 1/pB
    r0 = fmaf(-2.0f, RA * d1, 1.0f);            // tanh = 1 - 2/d
    r1 = fmaf(-2.0f, RA * d0, 1.0f);
    r2 = fmaf(-2.0f, RB * d3, 1.0f);
    r3 = fmaf(-2.0f, RB * d2, 1.0f);
}

__global__ void __launch_bounds__(512, 1)
prop_stencil_kernel(const float* __restrict__ X,
                    const float* __restrict__ pred,
                    const float* __restrict__ w,
                    const float* __restrict__ a,
                    const float* __restrict__ bias,
                    const float* __restrict__ scalar_p,
                    float* __restrict__ out)
{
    __shared__ float buf[2][SROWS][NSIDE];      // 2 x 34 x 64 x 4 = 17.4 KB

    const int b    = blockIdx.x;
    const int tid  = threadIdx.x;
    const int wid  = tid >> 5;                  // 0..15 -> rows 4w..4w+3
    const int lane = tid & 31;                  // -> cols 2l, 2l+1
    const int r0   = wid << 2;
    const int c0   = lane << 1;

    // Zero rows 0 and 33 of both buffers (256 words).
    if (tid < 256) {
        const int bb = tid >> 7;
        const int rr = ((tid >> 6) & 1) ? (SROWS - 1) : 0;
        buf[bb][rr][tid & 63] = 0.0f;
    }

    const float K = scalar_p[0] * 2.88539008177793f;   // 2*scalar*log2(e)

    const float2* Xb = (const float2*)(X    + (size_t)b * HPIX);
    const float2* Pb = (const float2*)(pred + (size_t)b * HPIX);
    const float2* w2 = (const float2*)w;
    const float2* a2 = (const float2*)a;
    const float2* b2 = (const float2*)bias;

    // 8 pixels per thread. State packed (u64); invariants scalar.
    u64 u[4];
    float csx[4], csy[4], wkx[4], wky[4];
    #pragma unroll
    for (int k = 0; k < 4; k++) {
        const int i = (r0 + k) * 32 + lane;
        const float2 p  = Pb[i];
        const float2 x  = Xb[i];
        const float2 ww = w2[i];
        const float2 aa = a2[i];
        const float2 bs = b2[i];
        u[k] = pk(p.x, p.y);
        csx[k] = (((p.x == -1.0f) ? 0.0f : p.x) + bs.x + aa.x * x.x) * K;
        csy[k] = (((p.y == -1.0f) ? 0.0f : p.y) + bs.y + aa.y * x.y) * K;
        wkx[k] = ww.x * K;  wky[k] = ww.y * K;
    }

    // Border masks (fold image-edge zeroing into FFMA).
    const float zL = (lane == 0)  ? 0.0f : 1.0f;
    const float zR = (lane == 31) ? 0.0f : 1.0f;

    // Seed buffer 0's boundary rows: warp w stores row 4w -> slot 2w+1,
    // row 4w+3 -> slot 2w+2; reads top halo (4w-1) from slot 2w, bottom halo
    // (4w+4) from slot 2w+3; slots 0 and 33 are the zero border.
    *(u64*)&buf[0][2 * wid + 1][c0] = u[0];
    *(u64*)&buf[0][2 * wid + 2][c0] = u[3];
    __syncthreads();        // covers zero-fill + seeding, once.

    #pragma unroll
    for (int it = 0; it < ITERS; it++) {
        const float (*S)[NSIDE] = buf[it & 1];

        // ---- Phase 1: interior rows 1,2 — register-only stencil; issues
        // past the (deferred-blocking) barrier while other warps arrive. ----
        const u64 m01 = add2(u[0], u[1]);
        const u64 m23 = add2(u[2], u[3]);
        const u64 V1  = add2(m01, u[2]);        // rows 0+1+2
        const u64 V2  = add2(u[1], m23);        // rows 1+2+3

        float v1x, v1y, v2x, v2y;
        upk(V1, v1x, v1y);  upk(V2, v2x, v2y);
        const float VL1 = __shfl_up_sync(0xffffffffu, v1y, 1);
        const float VR1 = __shfl_down_sync(0xffffffffu, v1x, 1);
        const float VL2 = __shfl_up_sync(0xffffffffu, v2y, 1);
        const float VR2 = __shfl_down_sync(0xffffffffu, v2x, 1);
        const float h1 = v1x + v1y;
        const float h2 = v2x + v2y;
        const float t1x = fmaf(wkx[1], fmaf(VL1, zL, h1), csx[1]);
        const float t1y = fmaf(wky[1], fmaf(VR1, zR, h1), csy[1]);
        const float t2x = fmaf(wkx[2], fmaf(VL2, zL, h2), csx[2]);
        const float t2y = fmaf(wky[2], fmaf(VR2, zR, h2), csy[2]);
        float r1x, r1y, r2x, r2y;
        tanh4s(t1x, t1y, t2x, t2y, r1x, r1y, r2x, r2y);
        const u64 u1n = pk(r1x, r1y);
        const u64 u2n = pk(r2x, r2y);

        // ---- Phase 2: boundary rows 0,3 — consume neighbors' halo. ----
        const u64 top = *(const u64*)&S[2 * wid    ][c0];    // row 4w-1
        const u64 bot = *(const u64*)&S[2 * wid + 3][c0];    // row 4w+4
        const u64 V0 = add2(top, m01);
        const u64 V3 = add2(m23, bot);

        float v0x, v0y, v3x, v3y;
        upk(V0, v0x, v0y);  upk(V3, v3x, v3y);
        const float VL0 = __shfl_up_sync(0xffffffffu, v0y, 1);
        const float VR0 = __shfl_down_sync(0xffffffffu, v0x, 1);
        const float VL3 = __shfl_up_sync(0xffffffffu, v3y, 1);
        const float VR3 = __shfl_down_sync(0xffffffffu, v3x, 1);
        const float h0 = v0x + v0y;
        const float h3 = v3x + v3y;
        const float t0x = fmaf(wkx[0], fmaf(VL0, zL, h0), csx[0]);
        const float t0y = fmaf(wky[0], fmaf(VR0, zR, h0), csy[0]);
        const float t3x = fmaf(wkx[3], fmaf(VL3, zL, h3), csx[3]);
        const float t3y = fmaf(wky[3], fmaf(VR3, zR, h3), csy[3]);
        float r0x, r0y, r3x, r3y;
        tanh4s(t0x, t0y, t3x, t3y, r0x, r0y, r3x, r3y);
        u[0] = pk(r0x, r0y);
        u[3] = pk(r3x, r3y);

        if (it < ITERS - 1) {
            float (*D)[NSIDE] = buf[(it + 1) & 1];
            *(u64*)&D[2 * wid + 1][c0] = u[0];
            *(u64*)&D[2 * wid + 2][c0] = u[3];
            __syncthreads();    // single barrier per iteration (double buffer);
                                // next iter's phase 1 issues past it
                                // (deferred-blocking), blocking only at LDS.
        }

        u[1] = u1n;  u[2] = u2n;
    }

    // Final values straight from registers (64-bit stores).
    u64* ob = (u64*)(out + (size_t)b * HPIX);
    #pragma unroll
    for (int k = 0; k < 4; k++)
        ob[(r0 + k) * 32 + lane] = u[k];
}

extern "C" void kernel_launch(void* const* d_in, const int* in_sizes, int n_in,
                              void* d_out, int out_size)
{
    const float* X      = (const float*)d_in[0];  // [B,4096]
    const float* pred   = (const float*)d_in[1];  // [B,4096]
    const float* w      = (const float*)d_in[2];  // [4096]
    const float* a      = (const float*)d_in[3];  // [4096]
    const float* bias   = (const float*)d_in[4];  // [4096]
    const float* scalar = (const float*)d_in[5];  // [1]
    // d_in[6] = hiddenWeight (unused: fixed 3x3 grid adjacency), d_in[7] = dtype
    float* out = (float*)d_out;

    const int B = in_sizes[0] / HPIX;             // 128
    prop_stencil_kernel<<<B, 512>>>(X, pred, w, a, bias, scalar, out);
}